// round 17
// baseline (speedup 1.0000x reference)
#include <cuda_runtime.h>
#include <cuda_bf16.h>
#include <math.h>
#include <stdint.h>

// ---------------------------------------------------------------------------
// Problem constants (fixed instance: B=4096, D=512). Scratch lives in
// __device__ globals. sim is never materialized; GEMM inputs are bf16.
// ---------------------------------------------------------------------------
#define BMAX 4096
#define DMAX 512
#define TEMP_INV (1.0f / 0.07f)
#define MARGIN 0.2f
#define MAXP 64
#define NBUCK 2048
#define NT_MAX 32

static __device__ __nv_bfloat16 g_vh[BMAX * DMAX];   // normalized vision (bf16)
static __device__ __nv_bfloat16 g_th[BMAX * DMAX];   // normalized text (bf16)
static __device__ int   g_ids32[BMAX];
static __device__ int   g_bcnt[NBUCK];
static __device__ int   g_bstart[NBUCK + 1];
static __device__ int   g_bitem[BMAX];
static __device__ int   g_np[BMAX];
static __device__ float g_mean2[2 * BMAX];
static __device__ float g_pd0[BMAX * MAXP];
static __device__ float g_pd1[BMAX * MAXP];
static __device__ float g_prow[(size_t)BMAX * NT_MAX];
static __device__ float g_pcol[(size_t)BMAX * NT_MAX];
static __device__ float g_partL[64];                 // per-block loss partials
static __device__ float g_partC[64];                 // per-block count partials
static __device__ int   g_done;                      // ticket for last-block reduce

// ---------------------------------------------------------------------------
// Reductions
// ---------------------------------------------------------------------------
__device__ __forceinline__ float warpSum(float v) {
#pragma unroll
    for (int o = 16; o; o >>= 1) v += __shfl_down_sync(0xffffffffu, v, o);
    return v;
}

__device__ __forceinline__ float blockSum(float v, float* sred, int nwarp) {
    v = warpSum(v);
    int w = threadIdx.x >> 5, l = threadIdx.x & 31;
    if (l == 0) sred[w] = v;
    __syncthreads();
    if (threadIdx.x < 32) {
        float x = (l < nwarp) ? sred[l] : 0.0f;
        x = warpSum(x);
        if (l == 0) sred[0] = x;
    }
    __syncthreads();
    float r = sred[0];
    __syncthreads();
    return r;
}

// ---------------------------------------------------------------------------
// 1. Combined pre-pass, grid (B, 3), 256 threads:
//    y = 0/1 : L2-normalize row x of vision/text -> bf16 (one float2 pass).
//    y = 2   : block x == 0 builds the id table; other x exit.
// ---------------------------------------------------------------------------
__global__ __launch_bounds__(256) void k_pre(const float* __restrict__ vis,
                                             const float* __restrict__ txt,
                                             const int* __restrict__ w,
                                             int n, int D) {
    int tid = threadIdx.x;
    if (blockIdx.y < 2) {
        __shared__ float sred[8];
        int row = blockIdx.x, which = blockIdx.y;
        const float* in = which ? txt : vis;
        __nv_bfloat16* out = which ? g_th : g_vh;
        const float* r = in + (size_t)row * D;
        float ss = 0.0f;
        for (int j = tid * 2; j < D; j += 512) {
            float2 v = *(const float2*)&r[j];
            ss += v.x * v.x + v.y * v.y;
        }
        float tot = blockSum(ss, sred, 8);
        float inv = 1.0f / fmaxf(sqrtf(tot), 1e-12f);
        for (int j = tid * 2; j < D; j += 512) {
            float2 v = *(const float2*)&r[j];
            __nv_bfloat162 h = __floats2bfloat162_rn(v.x * inv, v.y * inv);
            *(__nv_bfloat162*)&out[(size_t)row * D + j] = h;
        }
        return;
    }
    if (blockIdx.x != 0) return;

    // ---- id-table build (single block) ----
    __shared__ int flag;
    __shared__ int warp_tot[8];
    __shared__ int warp_base[8];
    if (tid == 0) { flag = 0; g_done = 0; }
    __syncthreads();
    for (int j = tid * 2 + 1; j < n; j += 512)
        if (w[j] != 0) flag = 1;   // benign race
    __syncthreads();
    int mode = flag ? 0 : 1;       // 0 = int32, 1 = int64
    for (int j = tid; j < n; j += 256)
        g_ids32[j] = mode ? (int)((const long long*)w)[j] : w[j];
    for (int b = tid; b < NBUCK; b += 256) g_bcnt[b] = 0;
    __syncthreads();
    for (int j = tid; j < n; j += 256)
        atomicAdd(&g_bcnt[g_ids32[j] & (NBUCK - 1)], 1);
    __syncthreads();
    int base = tid * (NBUCK / 256);
    int pre[NBUCK / 256];
    int loc = 0;
#pragma unroll
    for (int k = 0; k < NBUCK / 256; k++) { pre[k] = loc; loc += g_bcnt[base + k]; }
    int lane = tid & 31, wd = tid >> 5;
    int v = loc;
#pragma unroll
    for (int o = 1; o < 32; o <<= 1) {
        int t = __shfl_up_sync(0xffffffffu, v, o);
        if (lane >= o) v += t;
    }
    if (lane == 31) warp_tot[wd] = v;
    __syncthreads();
    if (tid == 0) {
        int a = 0;
        for (int i = 0; i < 8; i++) { warp_base[i] = a; a += warp_tot[i]; }
    }
    __syncthreads();
    int excl = warp_base[wd] + v - loc;
#pragma unroll
    for (int k = 0; k < NBUCK / 256; k++) g_bstart[base + k] = excl + pre[k];
    if (tid == 0) g_bstart[NBUCK] = n;
    __syncthreads();
    for (int b = tid; b < NBUCK; b += 256) g_bcnt[b] = g_bstart[b];
    __syncthreads();
    for (int j = tid; j < n; j += 256) {
        int b = g_ids32[j] & (NBUCK - 1);
        int p = atomicAdd(&g_bcnt[b], 1);
        g_bitem[p] = j;
    }
}

// ---------------------------------------------------------------------------
// 2. Pairs: one block (128 threads) per anchor row. Positive dots in fp32
//    FROM THE bf16-ROUNDED inputs, plus per-direction mean_pos.
// ---------------------------------------------------------------------------
__global__ __launch_bounds__(128) void k_pairs(int N, int D) {
    __shared__ float sred[4];
    __shared__ int s_pos[MAXP];
    __shared__ int s_np;
    int r = blockIdx.x;
    int tid = threadIdx.x;
    int myid = g_ids32[r];

    if (tid == 0) {
        int b = myid & (NBUCK - 1);
        int np = 0;
        for (int p = g_bstart[b]; p < g_bstart[b + 1]; p++) {
            int j = g_bitem[p];
            if (g_ids32[j] == myid && np < MAXP) s_pos[np++] = j;
        }
        for (int i = 1; i < np; i++) {
            int x = s_pos[i], k = i - 1;
            while (k >= 0 && s_pos[k] > x) { s_pos[k + 1] = s_pos[k]; k--; }
            s_pos[k + 1] = x;
        }
        s_np = np;
    }
    __syncthreads();
    int np = s_np;
    const __nv_bfloat162* vr = (const __nv_bfloat162*)&g_vh[(size_t)r * D];
    const __nv_bfloat162* tr = (const __nv_bfloat162*)&g_th[(size_t)r * D];
    float m0 = 0.0f, m1 = 0.0f;
    for (int k = 0; k < np; k++) {
        int j = s_pos[k];
        const __nv_bfloat162* vj = (const __nv_bfloat162*)&g_vh[(size_t)j * D];
        const __nv_bfloat162* tj = (const __nv_bfloat162*)&g_th[(size_t)j * D];
        float p0 = 0.0f, p1 = 0.0f;
        for (int d = tid; d < D / 2; d += 128) {
            float2 a0 = __bfloat1622float2(vr[d]);
            float2 b0 = __bfloat1622float2(tj[d]);
            p0 += a0.x * b0.x + a0.y * b0.y;
            float2 a1 = __bfloat1622float2(vj[d]);
            float2 b1 = __bfloat1622float2(tr[d]);
            p1 += a1.x * b1.x + a1.y * b1.y;
        }
        float d0 = blockSum(p0, sred, 4);
        float d1 = blockSum(p1, sred, 4);
        if (tid == 0) { g_pd0[r * MAXP + k] = d0; g_pd1[r * MAXP + k] = d1; }
        m0 += d0; m1 += d1;
    }
    if (tid == 0) {
        float fn = fmaxf((float)np, 1.0f);
        g_mean2[r] = m0 / fn;
        g_mean2[BMAX + r] = m1 / fn;
        g_np[r] = np;
    }
}

// ---------------------------------------------------------------------------
// 3. Tensor-core GEMM NT (bf16 mma.m16n8k16 + ldmatrix), 3-stage cp.async
//    ring with ONE barrier per iteration (wait -> sync -> fill(kt+2) -> MMA;
//    the sync proves slot (kt+2)%3 — stage kt-1's slot — is drained), and
//    the register-resident fused loss epilogue.
// ---------------------------------------------------------------------------
#define SMSB 144                       // smem row stride in BYTES
#define STAGE_B (2 * 128 * SMSB)       // A + B stage bytes (36864)
#define GEMM_SMEM (3 * STAGE_B)        // 110592 B (x2 CTA = 221184 <= SM cap)

__device__ __forceinline__ void cp16s(uint32_t dst, const void* src) {
    asm volatile("cp.async.cg.shared.global [%0], [%1], 16;" :: "r"(dst), "l"(src));
}

__device__ __forceinline__ void ldm_x4(uint32_t* r, uint32_t addr) {
    asm volatile("ldmatrix.sync.aligned.m8n8.x4.shared.b16 {%0,%1,%2,%3}, [%4];"
                 : "=r"(r[0]), "=r"(r[1]), "=r"(r[2]), "=r"(r[3]) : "r"(addr));
}

__device__ __forceinline__ void mma_bf16(float* c, const uint32_t* a,
                                         uint32_t b0, uint32_t b1) {
    asm("mma.sync.aligned.m16n8k16.row.col.f32.bf16.bf16.f32 "
        "{%0,%1,%2,%3}, {%4,%5,%6,%7}, {%8,%9}, {%0,%1,%2,%3};"
        : "+f"(c[0]), "+f"(c[1]), "+f"(c[2]), "+f"(c[3])
        : "r"(a[0]), "r"(a[1]), "r"(a[2]), "r"(a[3]), "r"(b0), "r"(b1));
}

__global__ __launch_bounds__(256, 2) void k_gemm_bf16(int N, int D) {
    extern __shared__ float sm[];
    uint32_t smb = (uint32_t)__cvta_generic_to_shared(sm);

    const __nv_bfloat16* __restrict__ A = g_vh;
    const __nv_bfloat16* __restrict__ Bm = g_th;
    int tid = threadIdx.x;
    int wid = tid >> 5, lane = tid & 31;
    int mo = (wid >> 2) * 64;
    int no = (wid & 3) * 32;
    int row0 = blockIdx.y * 128, col0 = blockIdx.x * 128;

    int tile = lane >> 3, trow = lane & 7;
    int ld_row = trow + (tile & 1) * 8;
    int ld_kofB = (tile >> 1) * 16;

    float acc[4][4][4];
#pragma unroll
    for (int ms = 0; ms < 4; ms++)
#pragma unroll
        for (int ns = 0; ns < 4; ns++)
#pragma unroll
            for (int q = 0; q < 4; q++) acc[ms][ns][q] = 0.0f;

    const int KT = D >> 6;   // 64-element k tiles

#define FILL(sidx, kt_) do {                                                   \
        uint32_t sa = smb + (uint32_t)(sidx) * STAGE_B;                        \
        uint32_t sb = sa + 128 * SMSB;                                         \
        int kb = (kt_) << 6;                                                   \
        _Pragma("unroll")                                                      \
        for (int q = 0; q < 4; q++) {                                          \
            int f = tid + q * 256;                                             \
            int rr = f >> 3, c16 = f & 7;                                      \
            cp16s(sa + (uint32_t)(rr * SMSB + c16 * 16),                       \
                  &A[(size_t)(row0 + rr) * D + kb + c16 * 8]);                 \
            cp16s(sb + (uint32_t)(rr * SMSB + c16 * 16),                       \
                  &Bm[(size_t)(col0 + rr) * D + kb + c16 * 8]);                \
        }                                                                      \
        asm volatile("cp.async.commit_group;");                                \
    } while (0)

    FILL(0, 0);
    if (KT > 1) FILL(1, 1);

    for (int kt = 0; kt < KT; kt++) {
        int s = kt % 3;
        // Fills committed so far: 0..min(kt+1, KT-1). Need fill kt complete.
        if (kt + 1 < KT) asm volatile("cp.async.wait_group 1;");
        else             asm volatile("cp.async.wait_group 0;");
        __syncthreads();
        // Prefetch stage kt+2 into slot (kt+2)%3 (drained per barrier proof).
        if (kt + 2 < KT) FILL((kt + 2) % 3, kt + 2);

        uint32_t sa = smb + (uint32_t)s * STAGE_B;
        uint32_t sb = sa + 128 * SMSB;
        uint32_t a_base = sa + (uint32_t)((mo + ld_row) * SMSB + ld_kofB);
        uint32_t b_base = sb + (uint32_t)((no + ld_row) * SMSB + ld_kofB);

#pragma unroll
        for (int kk = 0; kk < 4; kk++) {
            uint32_t a[4][4], b[2][4];
#pragma unroll
            for (int ms = 0; ms < 4; ms++)
                ldm_x4(a[ms], a_base + (uint32_t)(ms * 16 * SMSB + kk * 32));
#pragma unroll
            for (int g = 0; g < 2; g++)
                ldm_x4(b[g], b_base + (uint32_t)(g * 16 * SMSB + kk * 32));
#pragma unroll
            for (int ms = 0; ms < 4; ms++)
#pragma unroll
                for (int g = 0; g < 2; g++) {
                    mma_bf16(acc[ms][g * 2],     a[ms], b[g][0], b[g][2]);
                    mma_bf16(acc[ms][g * 2 + 1], a[ms], b[g][1], b[g][3]);
                }
        }
        // no trailing barrier: next iteration's top barrier covers drain
    }

    // ---- Register-resident epilogue ----
    __syncthreads();   // all ldmatrix done; stage smem reusable
    float* rowbuf = sm;            // [128][4] per-nwarp row partials
    float* colbuf = sm + 512;      // [128][2] per-mwarp col partials
    float* s_em   = sm + 768;      // [128] exp(m_col/T)
    float* s_el   = sm + 896;      // [128] exp((m_col-M)/T)

    if (tid < 128) {
        float m = g_mean2[BMAX + col0 + tid];
        s_em[tid] = __expf(m * TEMP_INV);
        s_el[tid] = __expf((m - MARGIN) * TEMP_INV);
    }
    __syncthreads();

    int lq = lane >> 2, lm4 = lane & 3;
    float rmean[4][2];
#pragma unroll
    for (int ms = 0; ms < 4; ms++) {
        rmean[ms][0] = g_mean2[row0 + mo + ms * 16 + lq];
        rmean[ms][1] = g_mean2[row0 + mo + ms * 16 + lq + 8];
    }
    float cem[4][2], cel[4][2];
#pragma unroll
    for (int ns = 0; ns < 4; ns++) {
#pragma unroll
        for (int par = 0; par < 2; par++) {
            int c = no + ns * 8 + 2 * lm4 + par;
            cem[ns][par] = s_em[c];
            cel[ns][par] = s_el[c];
        }
    }

    float rsum[4][2] = {};
    float csum[4][2] = {};
#pragma unroll
    for (int ms = 0; ms < 4; ms++)
#pragma unroll
        for (int h = 0; h < 2; h++) {
            float m = rmean[ms][h], lo = m - MARGIN;
#pragma unroll
            for (int ns = 0; ns < 4; ns++)
#pragma unroll
                for (int par = 0; par < 2; par++) {
                    float s = acc[ms][ns][h * 2 + par];
                    float e = __expf(s * TEMP_INV);
                    float w0 = (s < m && s > lo) ? 2.0f : 1.0f;
                    rsum[ms][h] = fmaf(e, w0, rsum[ms][h]);
                    float w1 = (e < cem[ns][par] && e > cel[ns][par]) ? 2.0f : 1.0f;
                    csum[ns][par] = fmaf(e, w1, csum[ns][par]);
                }
        }

#pragma unroll
    for (int ms = 0; ms < 4; ms++)
#pragma unroll
        for (int h = 0; h < 2; h++) {
            float v = rsum[ms][h];
            v += __shfl_xor_sync(0xffffffffu, v, 1);
            v += __shfl_xor_sync(0xffffffffu, v, 2);
            if (lm4 == 0)
                rowbuf[(mo + ms * 16 + lq + 8 * h) * 4 + (wid & 3)] = v;
        }
#pragma unroll
    for (int ns = 0; ns < 4; ns++)
#pragma unroll
        for (int par = 0; par < 2; par++) {
            float v = csum[ns][par];
            v += __shfl_xor_sync(0xffffffffu, v, 4);
            v += __shfl_xor_sync(0xffffffffu, v, 8);
            v += __shfl_xor_sync(0xffffffffu, v, 16);
            if (lq == 0)
                colbuf[(no + ns * 8 + 2 * lm4 + par) * 2 + (wid >> 2)] = v;
        }
    __syncthreads();

    if (tid < 128) {
        float r = rowbuf[tid * 4] + rowbuf[tid * 4 + 1] +
                  rowbuf[tid * 4 + 2] + rowbuf[tid * 4 + 3];
        g_prow[(size_t)(row0 + tid) * gridDim.x + blockIdx.x] = r;
    } else {
        int c = tid - 128;
        g_pcol[(size_t)(col0 + c) * gridDim.y + blockIdx.y] =
            colbuf[c * 2] + colbuf[c * 2 + 1];
    }
}

// ---------------------------------------------------------------------------
// 4. Final: grid of 64 blocks (256 threads). Each warp processes 8 rows:
//    reduce 32 partials/dir, subtract positives (dir-1 in e-space, matching
//    the epilogue), sum log1p terms. Block partial -> g_partL/g_partC; the
//    LAST block (atomic ticket + fences) reduces the 64 partials in fixed
//    order and writes the scalar. Ticket reset for graph replay.
// ---------------------------------------------------------------------------
__global__ __launch_bounds__(256) void k_final(float* __restrict__ out, int N) {
    __shared__ float sred[8];
    int w = threadIdx.x >> 5;
    int lane = threadIdx.x & 31;
    int nt = N >> 7;
    int rows_per_block = (N + gridDim.x - 1) / gridDim.x;   // 64 for B=4096
    int r0 = blockIdx.x * rows_per_block;

    float myL = 0.0f, myC = 0.0f;
    for (int rr = w; rr < rows_per_block; rr += 8) {
        int r = r0 + rr;
        if (r >= N) break;
        float p0 = (lane < nt) ? g_prow[(size_t)r * nt + lane] : 0.0f;
        float p1 = (lane < nt) ? g_pcol[(size_t)r * nt + lane] : 0.0f;
        float neg0 = warpSum(p0);
        float neg1 = warpSum(p1);
        if (lane == 0) {
            int np = g_np[r];
            float m0 = g_mean2[r], m1 = g_mean2[BMAX + r];
            float lo0 = m0 - MARGIN;
            float em1 = __expf(m1 * TEMP_INV);
            float el1 = __expf((m1 - MARGIN) * TEMP_INV);
            float sub0 = 0.0f, sub1 = 0.0f;
            for (int k = 0; k < np; k++) {
                float d0 = g_pd0[r * MAXP + k], d1 = g_pd1[r * MAXP + k];
                sub0 += ((d0 < m0 && d0 > lo0) ? 2.0f : 1.0f) * __expf(d0 * TEMP_INV);
                float e1 = __expf(d1 * TEMP_INV);
                sub1 += ((e1 < em1 && e1 > el1) ? 2.0f : 1.0f) * e1;
            }
            float na0 = neg0 - sub0, na1 = neg1 - sub1;
            float ls = 0.0f;
            for (int k = 0; k < np; k++) {
                ls += log1pf(na0 * __expf(-g_pd0[r * MAXP + k] * TEMP_INV));
                ls += log1pf(na1 * __expf(-g_pd1[r * MAXP + k] * TEMP_INV));
            }
            bool valid = (np > 0) && (np < N);
            myL += valid ? ls : 0.0f;
            myC += (float)np;
        }
    }
    float bL = blockSum(myL, sred, 8);
    float bC = blockSum(myC, sred, 8);
    if (threadIdx.x == 0) {
        g_partL[blockIdx.x] = bL;
        g_partC[blockIdx.x] = bC;
        __threadfence();
        int t = atomicAdd(&g_done, 1);
        if (t == (int)gridDim.x - 1) {
            float sa = 0.0f, sc = 0.0f;
            for (int i = 0; i < (int)gridDim.x; i++) {
                sa += g_partL[i];
                sc += g_partC[i];
            }
            out[0] = (sc > 0.0f) ? sa / (2.0f * fmaxf(sc, 1.0f)) : 0.0f;
            g_done = 0;   // reset for graph replay determinism
        }
    }
}

// ---------------------------------------------------------------------------
// Launch: kernel launches only (graph-capture safe, allocation-free).
// ---------------------------------------------------------------------------
extern "C" void kernel_launch(void* const* d_in, const int* in_sizes, int n_in,
                              void* d_out, int out_size) {
    const float* vis = (const float*)d_in[0];
    const float* txt = (const float*)d_in[1];
    const void* ids = d_in[2];
    float* out = (float*)d_out;

    int B = in_sizes[2];
    int D = in_sizes[0] / B;
    if (B > BMAX) B = BMAX;
    if (D > DMAX) D = DMAX;

    cudaFuncSetAttribute(k_gemm_bf16,
                         cudaFuncAttributeMaxDynamicSharedMemorySize, GEMM_SMEM);

    dim3 pgrid(B, 3);
    k_pre<<<pgrid, 256>>>(vis, txt, (const int*)ids, B, D);

    k_pairs<<<B, 128>>>(B, D);

    dim3 ggrid(B / 128, B / 128);
    k_gemm_bf16<<<ggrid, 256, GEMM_SMEM>>>(B, D);

    k_final<<<64, 256>>>(out, B);
}